// round 15
// baseline (speedup 1.0000x reference)
#include <cuda_runtime.h>

// tokens: int32[4194304] (values in [0,128)), ls: float32[128,2,2], final (unused)
// output: float32[2] = row 0 of ordered product of ls[tokens[t]], last token applied twice.

#define TPB 256
#define TOK_PER_BLOCK 8192
#define NGRAN (TOK_PER_BLOCK / 4)      // 2048 granules (4 tokens each) per block
#define MAX_BLOCKS 4096

__device__ float4 g_part[MAX_BLOCKS];
__device__ unsigned g_count = 0;

// C = A @ B, row-major 2x2 packed in float4 (x=m00, y=m01, z=m10, w=m11)
__device__ __forceinline__ float4 mm2(float4 A, float4 B) {
    float4 C;
    C.x = fmaf(A.x, B.x, A.y * B.z);
    C.y = fmaf(A.x, B.y, A.y * B.w);
    C.z = fmaf(A.z, B.x, A.w * B.z);
    C.w = fmaf(A.z, B.y, A.w * B.w);
    return C;
}

// Order-preserving pairwise warp reduction; lane 0 ends with ordered product.
__device__ __forceinline__ float4 warp_reduce_ordered(float4 M, unsigned lane) {
    #pragma unroll
    for (int off = 1; off < 32; off <<= 1) {
        float4 B;
        B.x = __shfl_down_sync(0xffffffffu, M.x, off);
        B.y = __shfl_down_sync(0xffffffffu, M.y, off);
        B.z = __shfl_down_sync(0xffffffffu, M.z, off);
        B.w = __shfl_down_sync(0xffffffffu, M.w, off);
        if ((lane & (2 * off - 1)) == 0) M = mm2(M, B);
    }
    return M;
}

// 16B-granule XOR swizzle: strided write (g = 32-aligned + lane) AND
// consecutive-8 read (g = 8u+k) both land at the 4-way crossbar floor.
__device__ __forceinline__ unsigned swz(unsigned i) { return i ^ ((i >> 3) & 7u); }

__global__ void __launch_bounds__(TPB)
chain_gran_kernel(const int* __restrict__ tokens,
                  const float* __restrict__ ls,
                  float* __restrict__ out,
                  int n_tokens) {
    // Replicated table: entry j, replica r at byte j*128 + r*16.
    // Lane l reads replica (l&7) -> fixed bank group, uniform 4-way = floor.
    __shared__ __align__(16) char  s_tab[128 * 128];   // 16 KB
    __shared__ float4              s_prod[NGRAN];      // 32 KB granule products
    __shared__ float4              s_warp[TPB / 32];
    __shared__ bool                s_is_last;

    const unsigned tid  = threadIdx.x;
    const unsigned lane = tid & 31u;
    const unsigned wid  = tid >> 5;
    const unsigned nblk = gridDim.x;

    // ── Load 8 strided granules: perfectly coalesced (16B lane stride), MLP=8,
    //    straight to registers — no staging, no packing.
    const int4* __restrict__ tok4 = reinterpret_cast<const int4*>(tokens);
    const unsigned base = blockIdx.x * NGRAN;
    int4 t0 = tok4[base + tid];
    int4 t1 = tok4[base + tid + 256];
    int4 t2 = tok4[base + tid + 512];
    int4 t3 = tok4[base + tid + 768];
    int4 t4 = tok4[base + tid + 1024];
    int4 t5 = tok4[base + tid + 1280];
    int4 t6 = tok4[base + tid + 1536];
    int4 t7 = tok4[base + tid + 1792];

    // ── Replicated table build (rotated, conflict-free writes).
    if (tid < 128) {
        float4 e = reinterpret_cast<const float4*>(ls)[tid];
        #pragma unroll
        for (int r = 0; r < 8; r++) {
            unsigned r_eff = (r + tid) & 7u;
            *reinterpret_cast<float4*>(s_tab + tid * 128 + r_eff * 16) = e;
        }
    }
    __syncthreads();

    const unsigned rbase = (lane & 7u) * 16u;   // this lane's replica column
    #define TAB(tok) (*reinterpret_cast<const float4*>( \
        s_tab + (((unsigned)(tok) & 127u) << 7) + rbase))

    // ── Phase 1: 8 independent 4-token granule chains (depth 3 mm2, ILP 8).
    float4 G0 = TAB(t0.x), G1 = TAB(t1.x), G2 = TAB(t2.x), G3 = TAB(t3.x);
    float4 G4 = TAB(t4.x), G5 = TAB(t5.x), G6 = TAB(t6.x), G7 = TAB(t7.x);
    G0 = mm2(G0, TAB(t0.y));  G1 = mm2(G1, TAB(t1.y));
    G2 = mm2(G2, TAB(t2.y));  G3 = mm2(G3, TAB(t3.y));
    G4 = mm2(G4, TAB(t4.y));  G5 = mm2(G5, TAB(t5.y));
    G6 = mm2(G6, TAB(t6.y));  G7 = mm2(G7, TAB(t7.y));
    G0 = mm2(G0, TAB(t0.z));  G1 = mm2(G1, TAB(t1.z));
    G2 = mm2(G2, TAB(t2.z));  G3 = mm2(G3, TAB(t3.z));
    G4 = mm2(G4, TAB(t4.z));  G5 = mm2(G5, TAB(t5.z));
    G6 = mm2(G6, TAB(t6.z));  G7 = mm2(G7, TAB(t7.z));
    G0 = mm2(G0, TAB(t0.w));  G1 = mm2(G1, TAB(t1.w));
    G2 = mm2(G2, TAB(t2.w));  G3 = mm2(G3, TAB(t3.w));
    G4 = mm2(G4, TAB(t4.w));  G5 = mm2(G5, TAB(t5.w));
    G6 = mm2(G6, TAB(t6.w));  G7 = mm2(G7, TAB(t7.w));

    // Publish granule products (swizzled: 4-way floor on write and read).
    s_prod[swz(tid)]        = G0;
    s_prod[swz(tid + 256)]  = G1;
    s_prod[swz(tid + 512)]  = G2;
    s_prod[swz(tid + 768)]  = G3;
    s_prod[swz(tid + 1024)] = G4;
    s_prod[swz(tid + 1280)] = G5;
    s_prod[swz(tid + 1536)] = G6;
    s_prod[swz(tid + 1792)] = G7;
    __syncthreads();

    // ── Phase 2: thread u owns granules 8u..8u+7 = tokens [32u, 32u+32).
    //    swz(8u+k) = 8u + (k ^ (u&7)) -> registers named by k, order preserved.
    {
        const unsigned b8 = 8u * tid;
        const unsigned r  = tid & 7u;
        float4 q0 = s_prod[b8 + (0u ^ r)];
        float4 q1 = s_prod[b8 + (1u ^ r)];
        float4 q2 = s_prod[b8 + (2u ^ r)];
        float4 q3 = s_prod[b8 + (3u ^ r)];
        float4 q4 = s_prod[b8 + (4u ^ r)];
        float4 q5 = s_prod[b8 + (5u ^ r)];
        float4 q6 = s_prod[b8 + (6u ^ r)];
        float4 q7 = s_prod[b8 + (7u ^ r)];
        float4 P = mm2(mm2(mm2(q0, q1), mm2(q2, q3)),
                       mm2(mm2(q4, q5), mm2(q6, q7)));

        P = warp_reduce_ordered(P, lane);
        if (lane == 0) s_warp[wid] = P;
    }
    __syncthreads();

    if (tid == 0) {
        float4 R = s_warp[0];
        #pragma unroll
        for (int wI = 1; wI < TPB / 32; wI++) R = mm2(R, s_warp[wI]);
        g_part[blockIdx.x] = R;
        __threadfence();                      // publish partial before counting
        unsigned old = atomicAdd(&g_count, 1u);
        s_is_last = (old == nblk - 1);
    }
    __syncthreads();

    // ── Phase 3: last block combines all 512 partials in order.
    if (s_is_last) {
        __threadfence();
        const int base2 = tid * 2;            // 512/256 = 2 partials per thread

        float4 P0 = g_part[base2 + 0];
        float4 P1 = g_part[base2 + 1];
        float4 P  = mm2(P0, P1);

        P = warp_reduce_ordered(P, lane);
        if (lane == 0) s_warp[wid] = P;
        __syncthreads();

        if (tid == 0) {
            float4 R = s_warp[0];
            #pragma unroll
            for (int wI = 1; wI < TPB / 32; wI++) R = mm2(R, s_warp[wI]);

            // Faithful to reference: last token's matrix applied a second time.
            int last = tokens[n_tokens - 1];
            R = mm2(R, TAB(last));

            out[0] = R.x;   // v = [1,0] @ R -> row 0
            out[1] = R.y;

            atomicExch(&g_count, 0u);   // reset for next graph replay
        }
    }
    #undef TAB
}

extern "C" void kernel_launch(void* const* d_in, const int* in_sizes, int n_in,
                              void* d_out, int out_size) {
    const int*   tokens = (const int*)d_in[0];
    const float* ls     = (const float*)d_in[1];
    float* out = (float*)d_out;

    const int n = in_sizes[0];                 // 4194304
    const int nblocks = n / TOK_PER_BLOCK;     // 512

    chain_gran_kernel<<<nblocks, TPB>>>(tokens, ls, out, n);
}

// round 16
// speedup vs baseline: 1.0025x; 1.0025x over previous
#include <cuda_runtime.h>

// tokens: int32[4194304] (values in [0,128)), ls: float32[128,2,2], final (unused)
// output: float32[2] = row 0 of ordered product of ls[tokens[t]], last token applied twice.

#define TPB 1024
#define TOK_PER_THREAD 32
#define TOK_PER_BLOCK (TPB * TOK_PER_THREAD)   // 32768
#define NBLK 128                                // 4194304 / 32768

__device__ float4 g_part[NBLK];
__device__ unsigned g_count = 0;

// C = A @ B, row-major 2x2 packed in float4 (x=m00, y=m01, z=m10, w=m11)
__device__ __forceinline__ float4 mm2(float4 A, float4 B) {
    float4 C;
    C.x = fmaf(A.x, B.x, A.y * B.z);
    C.y = fmaf(A.x, B.y, A.y * B.w);
    C.z = fmaf(A.z, B.x, A.w * B.z);
    C.w = fmaf(A.z, B.y, A.w * B.w);
    return C;
}

// Order-preserving pairwise warp reduction; lane 0 ends with ordered product.
__device__ __forceinline__ float4 warp_reduce_ordered(float4 M, unsigned lane) {
    #pragma unroll
    for (int off = 1; off < 32; off <<= 1) {
        float4 B;
        B.x = __shfl_down_sync(0xffffffffu, M.x, off);
        B.y = __shfl_down_sync(0xffffffffu, M.y, off);
        B.z = __shfl_down_sync(0xffffffffu, M.z, off);
        B.w = __shfl_down_sync(0xffffffffu, M.w, off);
        if ((lane & (2 * off - 1)) == 0) M = mm2(M, B);
    }
    return M;
}

__global__ void __launch_bounds__(TPB)
chain_mega_kernel(const int* __restrict__ tokens,
                  const float* __restrict__ ls,
                  float* __restrict__ out,
                  int n_tokens) {
    // Replicated table: entry j, replica r at byte j*128 + r*16.
    // Lane l reads replica (l&7) -> fixed bank group, uniform 4-way = floor.
    // Built ONCE per SM (one block per SM).
    __shared__ __align__(16) char  s_tab[128 * 128];          // 16 KB
    __shared__ unsigned            s_pack[TOK_PER_BLOCK / 4]; // 32 KB packed tokens
    __shared__ float4              s_warp[TPB / 32];          // 32 warp partials
    __shared__ bool                s_is_last;

    const unsigned tid  = threadIdx.x;
    const unsigned lane = tid & 31u;
    const unsigned wid  = tid >> 5;

    // ── Stage tokens: 8 coalesced LDG.128 per thread (MLP=8); pack 4 tokens
    //    per 32-bit word (values < 128 fit in a byte).
    const int4* __restrict__ tok4 = reinterpret_cast<const int4*>(tokens);
    const unsigned blk_i4 = blockIdx.x * (TOK_PER_BLOCK / 4);

    int4 a[8];
    #pragma unroll
    for (int k = 0; k < 8; k++) a[k] = tok4[blk_i4 + tid + TPB * k];

    // ── Replicated table build (rotated, conflict-free writes), once per block.
    if (tid < 128) {
        float4 e = reinterpret_cast<const float4*>(ls)[tid];
        #pragma unroll
        for (int r = 0; r < 8; r++) {
            unsigned r_eff = (r + tid) & 7u;
            *reinterpret_cast<float4*>(s_tab + tid * 128 + r_eff * 16) = e;
        }
    }

    #pragma unroll
    for (int k = 0; k < 8; k++) {
        s_pack[tid + TPB * k] = (unsigned)a[k].x | ((unsigned)a[k].y << 8)
                              | ((unsigned)a[k].z << 16) | ((unsigned)a[k].w << 24);
    }
    __syncthreads();

    // ── Phase 1 (R10-verified body): 32 contiguous tokens via TWO LDS.128;
    //    four independent 8-token chains, tree-combined (order preserved).
    const uint4 w0 = reinterpret_cast<const uint4*>(s_pack)[2 * tid];
    const uint4 w1 = reinterpret_cast<const uint4*>(s_pack)[2 * tid + 1];
    const unsigned rbase = (lane & 7u) * 16u;   // this lane's replica column

    #define TAB(word, sh) (*reinterpret_cast<const float4*>( \
        s_tab + ((((word) >> (sh)) & 127u) << 7) + rbase))

    float4 A = TAB(w0.x, 0);
    float4 B = TAB(w0.z, 0);
    float4 C = TAB(w1.x, 0);
    float4 D = TAB(w1.z, 0);
    A = mm2(A, TAB(w0.x,  8));  B = mm2(B, TAB(w0.z,  8));
    C = mm2(C, TAB(w1.x,  8));  D = mm2(D, TAB(w1.z,  8));
    A = mm2(A, TAB(w0.x, 16));  B = mm2(B, TAB(w0.z, 16));
    C = mm2(C, TAB(w1.x, 16));  D = mm2(D, TAB(w1.z, 16));
    A = mm2(A, TAB(w0.x, 24));  B = mm2(B, TAB(w0.z, 24));
    C = mm2(C, TAB(w1.x, 24));  D = mm2(D, TAB(w1.z, 24));
    A = mm2(A, TAB(w0.y,  0));  B = mm2(B, TAB(w0.w,  0));
    C = mm2(C, TAB(w1.y,  0));  D = mm2(D, TAB(w1.w,  0));
    A = mm2(A, TAB(w0.y,  8));  B = mm2(B, TAB(w0.w,  8));
    C = mm2(C, TAB(w1.y,  8));  D = mm2(D, TAB(w1.w,  8));
    A = mm2(A, TAB(w0.y, 16));  B = mm2(B, TAB(w0.w, 16));
    C = mm2(C, TAB(w1.y, 16));  D = mm2(D, TAB(w1.w, 16));
    A = mm2(A, TAB(w0.y, 24));  B = mm2(B, TAB(w0.w, 24));
    C = mm2(C, TAB(w1.y, 24));  D = mm2(D, TAB(w1.w, 24));
    float4 M = mm2(mm2(A, B), mm2(C, D));
    #undef TAB

    // ── Phase 2: per-warp ordered shuffle reduce; then warp 0 reduces the
    //    32 warp partials with a second ordered shuffle reduce (depth 5).
    M = warp_reduce_ordered(M, lane);
    if (lane == 0) s_warp[wid] = M;
    __syncthreads();

    if (wid == 0) {
        float4 P = s_warp[lane];               // warp w's partial in lane w
        P = warp_reduce_ordered(P, lane);
        if (lane == 0) {
            g_part[blockIdx.x] = P;
            __threadfence();                   // publish partial before counting
            unsigned old = atomicAdd(&g_count, 1u);
            s_is_last = (old == NBLK - 1);
        }
    }
    __syncthreads();

    // ── Phase 3: last block combines all 128 partials in order (warps 0-3).
    if (s_is_last) {
        __threadfence();
        if (tid < NBLK) {
            float4 P = g_part[tid];
            P = warp_reduce_ordered(P, lane);
            if (lane == 0) s_warp[wid] = P;    // warps 0..3 -> s_warp[0..3]
        }
        __syncthreads();

        if (tid == 0) {
            float4 R = s_warp[0];
            R = mm2(R, s_warp[1]);
            R = mm2(R, s_warp[2]);
            R = mm2(R, s_warp[3]);

            // Faithful to reference: last token's matrix applied a second time.
            int last = tokens[n_tokens - 1];
            const unsigned rb0 = 0u;
            float4 L = *reinterpret_cast<const float4*>(s_tab + ((unsigned)last << 7) + rb0);
            R = mm2(R, L);

            out[0] = R.x;   // v = [1,0] @ R -> row 0
            out[1] = R.y;

            atomicExch(&g_count, 0u);   // reset for next graph replay
        }
    }
}

extern "C" void kernel_launch(void* const* d_in, const int* in_sizes, int n_in,
                              void* d_out, int out_size) {
    const int*   tokens = (const int*)d_in[0];
    const float* ls     = (const float*)d_in[1];
    float* out = (float*)d_out;

    const int n = in_sizes[0];                 // 4194304
    chain_mega_kernel<<<NBLK, TPB>>>(tokens, ls, out, n);
}